// round 2
// baseline (speedup 1.0000x reference)
#include <cuda_runtime.h>
#include <cstdint>

#define MDIM 4096
#define NDIM 4096
#define KDIM 4096
#define BM 128
#define BN 128
#define BK 32
#define PAD 4
#define LDS (BK + PAD)          // 36 floats per smem row (conflict-free fragment loads)
#define NTHREADS 256
#define NKTILES (KDIM / BK)     // 128
#define BUF_FLOATS (BM * LDS)   // one A or B buffer
#define SMEM_BYTES (4 * BUF_FLOATS * 4)  // 2 x (A+B) double-buffered = 73728 B

__device__ __forceinline__ uint32_t f2tf32(float x) {
    uint32_t r;
    asm volatile("cvt.rna.tf32.f32 %0, %1;" : "=r"(r) : "f"(x));
    return r;
}

__device__ __forceinline__ void cp_async16(uint32_t saddr, const float* g) {
    asm volatile("cp.async.cg.shared.global [%0], [%1], 16;" :: "r"(saddr), "l"(g));
}

__global__ __launch_bounds__(NTHREADS)
void gemm_tf32_kernel(const float* __restrict__ X, const float* __restrict__ W,
                      const float* __restrict__ bias, float* __restrict__ Out) {
    extern __shared__ float smem[];
    float* As = smem;                       // [2][BM][LDS]
    float* Bs = smem + 2 * BUF_FLOATS;      // [2][BN][LDS]

    const int tid  = threadIdx.x;
    const int warp = tid >> 5;
    const int lane = tid & 31;
    const int bm   = blockIdx.y;
    const int bn   = blockIdx.x;

    const int warp_m = (warp >> 2) * 64;    // 0 or 64
    const int warp_n = (warp & 3) * 32;     // 0,32,64,96

    // ---- global -> shared mapping: 4 float4 per thread per tile, each for A and B
    const int grow  = tid >> 3;             // 0..31 (+= 32 per i)
    const int gcol  = (tid & 7) * 4;        // float column, 16B aligned
    const float* xg = X + (size_t)(bm * BM + grow) * KDIM + gcol;
    const float* wg = W + (size_t)(bn * BN + grow) * KDIM + gcol;

    uint32_t as_addr = (uint32_t)__cvta_generic_to_shared(As + grow * LDS + gcol);
    uint32_t bs_addr = (uint32_t)__cvta_generic_to_shared(Bs + grow * LDS + gcol);
    const uint32_t buf_bytes = BUF_FLOATS * 4;

    float acc[4][4][4];
#pragma unroll
    for (int mi = 0; mi < 4; mi++)
#pragma unroll
        for (int ni = 0; ni < 4; ni++)
#pragma unroll
            for (int r = 0; r < 4; r++) acc[mi][ni][r] = 0.0f;

    const int qrow = lane >> 2;   // 0..7
    const int qcol = lane & 3;    // 0..3

    // ---- prologue: load tile 0 into buffer 0
    {
        const float* xp = xg;
        const float* wp = wg;
#pragma unroll
        for (int i = 0; i < 4; i++) {
            cp_async16(as_addr + i * (32 * LDS * 4), xp + (size_t)i * 32 * KDIM);
            cp_async16(bs_addr + i * (32 * LDS * 4), wp + (size_t)i * 32 * KDIM);
        }
        asm volatile("cp.async.commit_group;");
    }

#pragma unroll 1
    for (int kb = 0; kb < NKTILES; kb++) {
        const int buf = kb & 1;

        if (kb + 1 < NKTILES) {
            const float* xp = xg + (size_t)(kb + 1) * BK;
            const float* wp = wg + (size_t)(kb + 1) * BK;
            const uint32_t off = (buf ^ 1) * buf_bytes;
#pragma unroll
            for (int i = 0; i < 4; i++) {
                cp_async16(as_addr + off + i * (32 * LDS * 4), xp + (size_t)i * 32 * KDIM);
                cp_async16(bs_addr + off + i * (32 * LDS * 4), wp + (size_t)i * 32 * KDIM);
            }
            asm volatile("cp.async.commit_group;");
            asm volatile("cp.async.wait_group 1;");
        } else {
            asm volatile("cp.async.wait_group 0;");
        }
        __syncthreads();

        const float* A0 = As + buf * BUF_FLOATS + warp_m * LDS;
        const float* B0 = Bs + buf * BUF_FLOATS + warp_n * LDS;

#pragma unroll
        for (int kk = 0; kk < 4; kk++) {
            const int k0 = kk * 8 + qcol;

            uint32_t a[4][4];
#pragma unroll
            for (int mi = 0; mi < 4; mi++) {
                const float* ap = A0 + (mi * 16 + qrow) * LDS + k0;
                a[mi][0] = f2tf32(ap[0]);
                a[mi][1] = f2tf32(ap[8 * LDS]);
                a[mi][2] = f2tf32(ap[4]);
                a[mi][3] = f2tf32(ap[8 * LDS + 4]);
            }
            uint32_t b[4][2];
#pragma unroll
            for (int ni = 0; ni < 4; ni++) {
                const float* bp = B0 + (ni * 8 + qrow) * LDS + k0;
                b[ni][0] = f2tf32(bp[0]);
                b[ni][1] = f2tf32(bp[4]);
            }

#pragma unroll
            for (int mi = 0; mi < 4; mi++) {
#pragma unroll
                for (int ni = 0; ni < 4; ni++) {
                    asm volatile(
                        "mma.sync.aligned.m16n8k8.row.col.f32.tf32.tf32.f32 "
                        "{%0,%1,%2,%3}, {%4,%5,%6,%7}, {%8,%9}, {%0,%1,%2,%3};"
                        : "+f"(acc[mi][ni][0]), "+f"(acc[mi][ni][1]),
                          "+f"(acc[mi][ni][2]), "+f"(acc[mi][ni][3])
                        : "r"(a[mi][0]), "r"(a[mi][1]), "r"(a[mi][2]), "r"(a[mi][3]),
                          "r"(b[ni][0]), "r"(b[ni][1]));
                }
            }
        }
        __syncthreads();
    }

    // ---- epilogue: bias add + store (float2, 8B aligned: col0 is even)
    const int row0 = bm * BM + warp_m + qrow;
    const int col0 = bn * BN + warp_n + 2 * qcol;

    float2 bv[4];
#pragma unroll
    for (int ni = 0; ni < 4; ni++) {
        bv[ni].x = bias[col0 + ni * 8];
        bv[ni].y = bias[col0 + ni * 8 + 1];
    }

#pragma unroll
    for (int mi = 0; mi < 4; mi++) {
        const int r = row0 + mi * 16;
#pragma unroll
        for (int ni = 0; ni < 4; ni++) {
            const int c = col0 + ni * 8;
            float2 v0 = make_float2(acc[mi][ni][0] + bv[ni].x, acc[mi][ni][1] + bv[ni].y);
            float2 v1 = make_float2(acc[mi][ni][2] + bv[ni].x, acc[mi][ni][3] + bv[ni].y);
            *reinterpret_cast<float2*>(&Out[(size_t)r * NDIM + c]) = v0;
            *reinterpret_cast<float2*>(&Out[(size_t)(r + 8) * NDIM + c]) = v1;
        }
    }
}

extern "C" void kernel_launch(void* const* d_in, const int* in_sizes, int n_in,
                              void* d_out, int out_size) {
    const float* x    = (const float*)d_in[0];
    const float* w    = (const float*)d_in[1];
    const float* bias = (const float*)d_in[2];
    float* out        = (float*)d_out;

    cudaFuncSetAttribute(gemm_tf32_kernel,
                         cudaFuncAttributeMaxDynamicSharedMemorySize, SMEM_BYTES);

    dim3 grid(NDIM / BN, MDIM / BM);   // 32 x 32 = 1024 CTAs
    gemm_tf32_kernel<<<grid, NTHREADS, SMEM_BYTES>>>(x, w, bias, out);
}